// round 12
// baseline (speedup 1.0000x reference)
#include <cuda_runtime.h>
#include <cuda_fp16.h>
#include <math.h>
#include <stdint.h>

#define NB 4
#define NP 8
#define NN 512
#define DM 128
#define NH 4
#define DK 32
#define NT 3
#define NROWS (NB*NP*NN)     // 16384
#define MAXNNZ 128
#define LISTD 132            // list dim: MAXNNZ + >=2 pad entries for prefetch
#define LDP 132              // smem row stride (floats) for tf32 GEMM tiles
#define LDH 68               // smem row stride (uint32 = half2) for fp16 tiles

// Scratch (device globals). fp16 intermediates to halve HBM traffic.
__device__ __half g_qkv[9][NROWS][DM];   // [t*3 + {Q,K,V}][row][d]
__device__ __half g_attn[NT][NROWS][DM]; // per-t attention output (fp16)
__device__ int    g_nnz[NT][NN];
__device__ int    g_colsT[NT][LISTD][NN];   // [t][i][n] -> coalesced over n
__device__ float  g_valsT[NT][LISTD][NN];

__constant__ int c_which[NT] = {0, 1, 3};

// ---------------------------------------------------------------------------
__device__ __forceinline__ uint32_t f2tf32(float f) {
    uint32_t r; asm("cvt.rna.tf32.f32 %0, %1;" : "=r"(r) : "f"(f)); return r;
}
__device__ __forceinline__ uint32_t pack_h2(float a, float b) {
    __half2 h = __floats2half2_rn(a, b);
    return *(uint32_t*)&h;
}
// m16n8k8 tf32 MMA, D += A*B (row x col)
__device__ __forceinline__ void mma8(float d[4], const uint32_t a[4], const uint32_t b[2]) {
    asm volatile("mma.sync.aligned.m16n8k8.row.col.f32.tf32.tf32.f32 "
        "{%0,%1,%2,%3}, {%4,%5,%6,%7}, {%8,%9}, {%0,%1,%2,%3};"
        : "+f"(d[0]), "+f"(d[1]), "+f"(d[2]), "+f"(d[3])
        : "r"(a[0]), "r"(a[1]), "r"(a[2]), "r"(a[3]), "r"(b[0]), "r"(b[1]));
}
// m16n8k16 fp16 MMA, fp32 accum, D += A*B (row x col)
__device__ __forceinline__ void mma16(float d[4], const uint32_t a[4], const uint32_t b[2]) {
    asm volatile("mma.sync.aligned.m16n8k16.row.col.f32.f16.f16.f32 "
        "{%0,%1,%2,%3}, {%4,%5,%6,%7}, {%8,%9}, {%0,%1,%2,%3};"
        : "+f"(d[0]), "+f"(d[1]), "+f"(d[2]), "+f"(d[3])
        : "r"(a[0]), "r"(a[1]), "r"(a[2]), "r"(a[3]), "r"(b[0]), "r"(b[1]));
}

// ===========================================================================
// Kernel 1: build transposed CSR of the selected transition matrices.
// Warp per row n; ballot compaction; [t][i][n] layout (coalesced over n).
// Writes 2 zero pad entries after the list for the prefetch pipeline.
// ===========================================================================
__global__ void build_csr_kernel(const float* __restrict__ tmall) {
    int wg   = (blockIdx.x * blockDim.x + threadIdx.x) >> 5;
    int lane = threadIdx.x & 31;
    if (wg >= NT * NN) return;
    int t = wg / NN, n = wg % NN;
    const float* row = tmall + ((size_t)c_which[t] * NN + n) * NN;
    int cnt = 0;
    for (int base = 0; base < NN; base += 32) {
        float v = row[base + lane];
        unsigned b = __ballot_sync(0xffffffffu, v != 0.0f);
        if (v != 0.0f) {
            int pos = cnt + __popc(b & ((1u << lane) - 1u));
            if (pos < MAXNNZ) { g_colsT[t][pos][n] = base + lane; g_valsT[t][pos][n] = v; }
        }
        cnt += __popc(b);
    }
    int cc = cnt < MAXNNZ ? cnt : MAXNNZ;
    if (lane < 2) {                       // zero pads at [cc] and [cc+1]
        g_colsT[t][cc + lane][n] = 0;
        g_valsT[t][cc + lane][n] = 0.0f;
    }
    if (lane == 0) g_nnz[t][n] = cc;
}

// ===========================================================================
// Kernel 2: QKV projections via fp16 mma.sync m16n8k16 (fp32 accumulate).
// grid = (256 tiles, 9 slots); 256 threads / 8 warps (2m x 4n of 32x32);
// 3 CTAs/SM (51KB smem). Output stored fp16.
// ===========================================================================
__global__ void __launch_bounds__(256, 3)
qkv_mma_kernel(const float* __restrict__ X,
               const float* __restrict__ Wq,
               const float* __restrict__ Wk,
               const float* __restrict__ Wv) {
    extern __shared__ uint32_t sm[];
    uint32_t* Xh = sm;                // [64][LDH] half2 units
    uint32_t* Wh = sm + 64 * LDH;     // [128][LDH]
    int tid = threadIdx.x, lane = tid & 31, wid = tid >> 5;
    int mw = wid & 1, nw = wid >> 1;
    int g = lane >> 2, q = lane & 3;
    int slot = blockIdx.y;
    int row0 = blockIdx.x * 64;

    const float* Wb[3] = {Wq, Wk, Wv};
    const float* W = Wb[slot % 3] + (size_t)(slot / 3) * DM * DM;

    for (int i = tid; i < 64 * 32; i += 256) {
        int r = i >> 5, k4 = (i & 31) << 2;
        float4 v = *(const float4*)(X + (size_t)(row0 + r) * DM + k4);
        uint2 p = make_uint2(pack_h2(v.x, v.y), pack_h2(v.z, v.w));
        *(uint2*)(Xh + r * LDH + (k4 >> 1)) = p;
    }
    for (int i = tid; i < 128 * 32; i += 256) {
        int r = i >> 5, k4 = (i & 31) << 2;
        float4 v = *(const float4*)(W + (size_t)r * DM + k4);
        uint2 p = make_uint2(pack_h2(v.x, v.y), pack_h2(v.z, v.w));
        *(uint2*)(Wh + r * LDH + (k4 >> 1)) = p;
    }
    __syncthreads();

    const uint32_t* abase = Xh + (mw * 32 + g) * LDH + q;
    const uint32_t* bbase = Wh + (nw * 32 + g) * LDH + q;

    float acc[2][4][4];
    #pragma unroll
    for (int t2 = 0; t2 < 2; t2++)
        #pragma unroll
        for (int j = 0; j < 4; j++)
            #pragma unroll
            for (int e = 0; e < 4; e++) acc[t2][j][e] = 0.f;

    #pragma unroll
    for (int ks = 0; ks < 8; ks++) {       // 8 steps of k=16
        int k0 = ks * 8;
        uint32_t a[2][4];
        #pragma unroll
        for (int t2 = 0; t2 < 2; t2++) {
            const uint32_t* ap = abase + t2 * 16 * LDH + k0;
            a[t2][0] = ap[0];            a[t2][1] = ap[8 * LDH];
            a[t2][2] = ap[4];            a[t2][3] = ap[8 * LDH + 4];
        }
        #pragma unroll
        for (int j = 0; j < 4; j++) {
            const uint32_t* bp = bbase + j * 8 * LDH + k0;
            uint32_t b[2]; b[0] = bp[0]; b[1] = bp[4];
            mma16(acc[0][j], a[0], b);
            mma16(acc[1][j], a[1], b);
        }
    }
    __half* outh = &g_qkv[slot][row0][0];
    #pragma unroll
    for (int t2 = 0; t2 < 2; t2++) {
        int r = mw * 32 + t2 * 16 + g;
        #pragma unroll
        for (int j = 0; j < 4; j++) {
            int c = nw * 32 + j * 8 + q * 2;
            *(uint32_t*)(outh + (size_t)r * DM + c)       = pack_h2(acc[t2][j][0], acc[t2][j][1]);
            *(uint32_t*)(outh + (size_t)(r + 8) * DM + c) = pack_h2(acc[t2][j][2], acc[t2][j][3]);
        }
    }
}

// ===========================================================================
// Kernel 3: sparse-masked attention. Block = (t,bp,h), 512 threads, one per
// query row n. K/V fp16->fp32 into R4 SMEM layout (stride-32, lane-rotated
// 4-phase reads). NEW: depth-2 software pipeline on the CSR (m, tv) loads --
// the loop was exposing ~250cyc of L2 latency per iteration. Split dot
// accumulator halves the FFMA chain. fp16 output.
// ===========================================================================
__global__ void __launch_bounds__(512, 1)
attn_kernel() {
    extern __shared__ float smf[];
    float* Ks = smf;               // [512][32]
    float* Vs = smf + 512 * 32;    // [512][32]
    int tid = threadIdx.x;
    int h = blockIdx.x;
    int t = blockIdx.y >> 5, bp = blockIdx.y & 31;

    const __half* Kg = &g_qkv[t * 3 + 1][(size_t)bp * NN][0];
    const __half* Vg = &g_qkv[t * 3 + 2][(size_t)bp * NN][0];
    for (int i = tid; i < 512 * 4; i += 512) {
        int m = i >> 2, c = i & 3;
        uint4 kk = *(const uint4*)(Kg + (size_t)m * DM + h * DK + c * 8);
        float2 f0 = __half22float2(*(__half2*)&kk.x);
        float2 f1 = __half22float2(*(__half2*)&kk.y);
        float2 f2 = __half22float2(*(__half2*)&kk.z);
        float2 f3 = __half22float2(*(__half2*)&kk.w);
        *(float4*)(Ks + m * 32 + c * 8)     = make_float4(f0.x, f0.y, f1.x, f1.y);
        *(float4*)(Ks + m * 32 + c * 8 + 4) = make_float4(f2.x, f2.y, f3.x, f3.y);
        uint4 vv = *(const uint4*)(Vg + (size_t)m * DM + h * DK + c * 8);
        f0 = __half22float2(*(__half2*)&vv.x);
        f1 = __half22float2(*(__half2*)&vv.y);
        f2 = __half22float2(*(__half2*)&vv.z);
        f3 = __half22float2(*(__half2*)&vv.w);
        *(float4*)(Vs + m * 32 + c * 8)     = make_float4(f0.x, f0.y, f1.x, f1.y);
        *(float4*)(Vs + m * 32 + c * 8 + 4) = make_float4(f2.x, f2.y, f3.x, f3.y);
    }
    __syncthreads();

    int n = tid;
    int gn = bp * NN + n;
    int rot = tid & 7;
    const float scale = 0.17677669529663687f;   // 1/sqrt(32), folded into Q
    float4 qr[8];
    const __half* Qg = &g_qkv[t * 3 + 0][gn][h * DK];
    #pragma unroll
    for (int j = 0; j < 8; j++) {
        int jj = (j + rot) & 7;
        uint2 qv = *(const uint2*)(Qg + jj * 4);
        float2 a = __half22float2(*(__half2*)&qv.x);
        float2 b = __half22float2(*(__half2*)&qv.y);
        qr[j] = make_float4(a.x * scale, a.y * scale, b.x * scale, b.y * scale);
    }
    int cnt = g_nnz[t][n];
    float Z = 0.f;
    float4 av[8];
    #pragma unroll
    for (int j = 0; j < 8; j++) av[j] = make_float4(0.f, 0.f, 0.f, 0.f);

    // depth-2 rolling prefetch of the CSR entries (pads make i+2 safe)
    int   m0 = g_colsT[t][0][n], m1 = g_colsT[t][1][n];
    float t0 = g_valsT[t][0][n], t1 = g_valsT[t][1][n];
    for (int i = 0; i < cnt; i++) {
        int   m2 = g_colsT[t][i + 2][n];
        float t2 = g_valsT[t][i + 2][n];
        const float* kb = Ks + m0 * 32;
        float s0 = 0.f, s1 = 0.f;
        #pragma unroll
        for (int j = 0; j < 8; j += 2) {
            int j0 = (j + rot) & 7, j1 = (j + 1 + rot) & 7;
            float4 ka = *(const float4*)(kb + j0 * 4);
            float4 kc = *(const float4*)(kb + j1 * 4);
            s0 += qr[j].x * ka.x + qr[j].y * ka.y + qr[j].z * ka.z + qr[j].w * ka.w;
            s1 += qr[j+1].x * kc.x + qr[j+1].y * kc.y + qr[j+1].z * kc.z + qr[j+1].w * kc.w;
        }
        float e = __expf(s0 + s1);
        Z += e;
        float we = t0 * e;
        const float* vb = Vs + m0 * 32;
        #pragma unroll
        for (int j = 0; j < 8; j++) {
            int jj = (j + rot) & 7;
            float4 v4 = *(const float4*)(vb + jj * 4);
            av[j].x += we * v4.x;
            av[j].y += we * v4.y;
            av[j].z += we * v4.z;
            av[j].w += we * v4.w;
        }
        m0 = m1; t0 = t1;
        m1 = m2; t1 = t2;
    }
    float inv = 1.f / Z;
    __half* outh = &g_attn[t][gn][h * DK];
    #pragma unroll
    for (int j = 0; j < 8; j++) {
        int jj = (j + rot) & 7;
        uint2 p = make_uint2(pack_h2(av[j].x * inv, av[j].y * inv),
                             pack_h2(av[j].z * inv, av[j].w * inv));
        *(uint2*)(outh + jj * 4) = p;
    }
}

// ===========================================================================
// Kernel 4: output projection via tf32 mma.sync (K=384 = 3 accumulated
// chunks), 512 threads / 16 warps; A staged from fp16 g_attn; fused
// residual + warp-per-row LayerNorm.
// ===========================================================================
__global__ void __launch_bounds__(512, 1)
outproj_mma_kernel(const float* __restrict__ X,
                   const float* __restrict__ Wo,
                   const float* __restrict__ gamma,
                   const float* __restrict__ beta,
                   float* __restrict__ out) {
    extern __shared__ uint32_t sm[];
    uint32_t* As = sm;                 // [128][LDP]
    uint32_t* Ws = sm + 128 * LDP;     // [128][LDP]
    float* Ys = (float*)sm;            // reuse As after GEMM
    int tid = threadIdx.x, lane = tid & 31, wid = tid >> 5;
    int mw = wid & 3, nw = wid >> 2;
    int g = lane >> 2, q = lane & 3;
    int row0 = blockIdx.x * 128;

    const uint32_t* abase = As + (mw * 32 + g) * LDP + q;
    const uint32_t* bbase = Ws + (nw * 32 + g) * LDP + q;

    float acc[2][4][4];
    #pragma unroll
    for (int t2 = 0; t2 < 2; t2++)
        #pragma unroll
        for (int j = 0; j < 4; j++)
            #pragma unroll
            for (int e = 0; e < 4; e++) acc[t2][j][e] = 0.f;

    for (int t = 0; t < NT; t++) {
        __syncthreads();
        for (int i = tid; i < 128 * 16; i += 512) {
            int r = i >> 4, k = (i & 15) << 3;
            uint4 a = *(const uint4*)(&g_attn[t][row0 + r][k]);
            float2 f0 = __half22float2(*(__half2*)&a.x);
            float2 f1 = __half22float2(*(__half2*)&a.y);
            float2 f2 = __half22float2(*(__half2*)&a.z);
            float2 f3 = __half22float2(*(__half2*)&a.w);
            uint32_t* d = As + r * LDP + k;
            d[0] = f2tf32(f0.x); d[1] = f2tf32(f0.y);
            d[2] = f2tf32(f1.x); d[3] = f2tf32(f1.y);
            d[4] = f2tf32(f2.x); d[5] = f2tf32(f2.y);
            d[6] = f2tf32(f3.x); d[7] = f2tf32(f3.y);
        }
        for (int i = tid; i < 128 * 32; i += 512) {
            int r = i >> 5, k = (i & 31) << 2;
            float4 w = *(const float4*)(Wo + (size_t)r * (NT * DM) + t * DM + k);
            uint32_t* d2 = Ws + r * LDP + k;
            d2[0] = f2tf32(w.x); d2[1] = f2tf32(w.y); d2[2] = f2tf32(w.z); d2[3] = f2tf32(w.w);
        }
        __syncthreads();
        #pragma unroll 4
        for (int ks = 0; ks < 16; ks++) {
            int k0 = ks * 8;
            uint32_t a[2][4];
            #pragma unroll
            for (int t2 = 0; t2 < 2; t2++) {
                const uint32_t* ap = abase + t2 * 16 * LDP + k0;
                a[t2][0] = ap[0]; a[t2][1] = ap[8 * LDP];
                a[t2][2] = ap[4]; a[t2][3] = ap[8 * LDP + 4];
            }
            #pragma unroll
            for (int j = 0; j < 4; j++) {
                const uint32_t* bp = bbase + j * 8 * LDP + k0;
                uint32_t b[2]; b[0] = bp[0]; b[1] = bp[4];
                mma8(acc[0][j], a[0], b);
                mma8(acc[1][j], a[1], b);
            }
        }
    }
    __syncthreads();
    #pragma unroll
    for (int t2 = 0; t2 < 2; t2++) {
        int r = mw * 32 + t2 * 16 + g;
        #pragma unroll
        for (int j = 0; j < 4; j++) {
            int c = nw * 32 + j * 8 + q * 2;
            *(float2*)(Ys + r * LDP + c)       = make_float2(acc[t2][j][0], acc[t2][j][1]);
            *(float2*)(Ys + (r + 8) * LDP + c) = make_float2(acc[t2][j][2], acc[t2][j][3]);
        }
    }
    __syncthreads();
    for (int r = wid; r < 128; r += 16) {
        float4 y  = *(float4*)(Ys + r * LDP + lane * 4);
        float4 xv = *(const float4*)(X + (size_t)(row0 + r) * DM + lane * 4);
        float v0 = y.x + xv.x, v1 = y.y + xv.y, v2 = y.z + xv.z, v3 = y.w + xv.w;
        float s  = v0 + v1 + v2 + v3;
        float s2 = v0 * v0 + v1 * v1 + v2 * v2 + v3 * v3;
        #pragma unroll
        for (int off = 16; off; off >>= 1) {
            s  += __shfl_xor_sync(0xffffffffu, s,  off);
            s2 += __shfl_xor_sync(0xffffffffu, s2, off);
        }
        float mu = s * (1.f / DM);
        float var = s2 * (1.f / DM) - mu * mu;
        float rs = rsqrtf(var + 1e-5f);
        float4 gv = *(const float4*)(gamma + lane * 4);
        float4 bv = *(const float4*)(beta + lane * 4);
        float4 res = make_float4((v0 - mu) * rs * gv.x + bv.x,
                                 (v1 - mu) * rs * gv.y + bv.y,
                                 (v2 - mu) * rs * gv.z + bv.z,
                                 (v3 - mu) * rs * gv.w + bv.w);
        *(float4*)(out + (size_t)(row0 + r) * DM + lane * 4) = res;
    }
}

// ===========================================================================
extern "C" void kernel_launch(void* const* d_in, const int* in_sizes, int n_in,
                              void* d_out, int out_size) {
    const float* inputs = (const float*)d_in[0];
    const float* tm     = (const float*)d_in[2];
    const float* Wq     = (const float*)d_in[3];
    const float* Wk     = (const float*)d_in[4];
    const float* Wv     = (const float*)d_in[5];
    const float* Wo     = (const float*)d_in[6];
    const float* gamma  = (const float*)d_in[7];
    const float* beta   = (const float*)d_in[8];
    float* out = (float*)d_out;

    int smem_qkv  = (64 + 128) * LDH * (int)sizeof(uint32_t); // 52224
    int smem_attn = 2 * 512 * 32 * (int)sizeof(float);        // 131072
    int smem_out  = 2 * 128 * LDP * (int)sizeof(float);       // 135168
    cudaFuncSetAttribute(qkv_mma_kernel,     cudaFuncAttributeMaxDynamicSharedMemorySize, smem_qkv);
    cudaFuncSetAttribute(attn_kernel,        cudaFuncAttributeMaxDynamicSharedMemorySize, smem_attn);
    cudaFuncSetAttribute(outproj_mma_kernel, cudaFuncAttributeMaxDynamicSharedMemorySize, smem_out);

    build_csr_kernel<<<(NT * NN * 32 + 255) / 256, 256>>>(tm);
    qkv_mma_kernel<<<dim3(NROWS / 64, 9), 256, smem_qkv>>>(inputs, Wq, Wk, Wv);
    attn_kernel<<<dim3(NH, NT * NB * NP), 512, smem_attn>>>();
    outproj_mma_kernel<<<NROWS / 128, 512, smem_out>>>(inputs, Wo, gamma, beta, out);
}

// round 13
// speedup vs baseline: 1.1181x; 1.1181x over previous
#include <cuda_runtime.h>
#include <cuda_fp16.h>
#include <math.h>
#include <stdint.h>

#define NB 4
#define NP 8
#define NN 512
#define DM 128
#define NH 4
#define DK 32
#define NT 3
#define NROWS (NB*NP*NN)     // 16384
#define MAXNNZ 128
#define LISTD 132
#define LDP 132              // smem row stride (floats) for tf32 GEMM tiles
#define LDH 68               // smem row stride (uint32 = half2) for fp16 tiles

// Scratch (device globals). fp16 intermediates to halve HBM traffic.
__device__ __half g_qkv[9][NROWS][DM];   // [t*3 + {Q,K,V}][row][d]
__device__ __half g_attn[NT][NROWS][DM]; // per-t attention output (fp16)
__device__ int    g_nnz[NT][NN];
__device__ int    g_colsT[NT][LISTD][NN];   // [t][i][n] -> coalesced over n
__device__ float  g_valsT[NT][LISTD][NN];

__constant__ int c_which[NT] = {0, 1, 3};

// ---------------------------------------------------------------------------
__device__ __forceinline__ uint32_t f2tf32(float f) {
    uint32_t r; asm("cvt.rna.tf32.f32 %0, %1;" : "=r"(r) : "f"(f)); return r;
}
__device__ __forceinline__ uint32_t pack_h2(float a, float b) {
    __half2 h = __floats2half2_rn(a, b);
    return *(uint32_t*)&h;
}
// m16n8k8 tf32 MMA, D += A*B (row x col)
__device__ __forceinline__ void mma8(float d[4], const uint32_t a[4], const uint32_t b[2]) {
    asm volatile("mma.sync.aligned.m16n8k8.row.col.f32.tf32.tf32.f32 "
        "{%0,%1,%2,%3}, {%4,%5,%6,%7}, {%8,%9}, {%0,%1,%2,%3};"
        : "+f"(d[0]), "+f"(d[1]), "+f"(d[2]), "+f"(d[3])
        : "r"(a[0]), "r"(a[1]), "r"(a[2]), "r"(a[3]), "r"(b[0]), "r"(b[1]));
}
// m16n8k16 fp16 MMA, fp32 accum, D += A*B (row x col)
__device__ __forceinline__ void mma16(float d[4], const uint32_t a[4], const uint32_t b[2]) {
    asm volatile("mma.sync.aligned.m16n8k16.row.col.f32.f16.f16.f32 "
        "{%0,%1,%2,%3}, {%4,%5,%6,%7}, {%8,%9}, {%0,%1,%2,%3};"
        : "+f"(d[0]), "+f"(d[1]), "+f"(d[2]), "+f"(d[3])
        : "r"(a[0]), "r"(a[1]), "r"(a[2]), "r"(a[3]), "r"(b[0]), "r"(b[1]));
}

// ===========================================================================
// Kernel 1: build transposed CSR of the selected transition matrices.
// ===========================================================================
__global__ void build_csr_kernel(const float* __restrict__ tmall) {
    int wg   = (blockIdx.x * blockDim.x + threadIdx.x) >> 5;
    int lane = threadIdx.x & 31;
    if (wg >= NT * NN) return;
    int t = wg / NN, n = wg % NN;
    const float* row = tmall + ((size_t)c_which[t] * NN + n) * NN;
    int cnt = 0;
    for (int base = 0; base < NN; base += 32) {
        float v = row[base + lane];
        unsigned b = __ballot_sync(0xffffffffu, v != 0.0f);
        if (v != 0.0f) {
            int pos = cnt + __popc(b & ((1u << lane) - 1u));
            if (pos < MAXNNZ) { g_colsT[t][pos][n] = base + lane; g_valsT[t][pos][n] = v; }
        }
        cnt += __popc(b);
    }
    if (lane == 0) g_nnz[t][n] = cnt < MAXNNZ ? cnt : MAXNNZ;
}

// ===========================================================================
// Kernel 2: QKV projections via fp16 mma.sync m16n8k16 (fp32 accumulate).
// grid = (256 tiles, 9 slots); 256 threads / 8 warps; 3 CTAs/SM. fp16 out.
// ===========================================================================
__global__ void __launch_bounds__(256, 3)
qkv_mma_kernel(const float* __restrict__ X,
               const float* __restrict__ Wq,
               const float* __restrict__ Wk,
               const float* __restrict__ Wv) {
    extern __shared__ uint32_t sm[];
    uint32_t* Xh = sm;                // [64][LDH] half2 units
    uint32_t* Wh = sm + 64 * LDH;     // [128][LDH]
    int tid = threadIdx.x, lane = tid & 31, wid = tid >> 5;
    int mw = wid & 1, nw = wid >> 1;
    int g = lane >> 2, q = lane & 3;
    int slot = blockIdx.y;
    int row0 = blockIdx.x * 64;

    const float* Wb[3] = {Wq, Wk, Wv};
    const float* W = Wb[slot % 3] + (size_t)(slot / 3) * DM * DM;

    for (int i = tid; i < 64 * 32; i += 256) {
        int r = i >> 5, k4 = (i & 31) << 2;
        float4 v = *(const float4*)(X + (size_t)(row0 + r) * DM + k4);
        uint2 p = make_uint2(pack_h2(v.x, v.y), pack_h2(v.z, v.w));
        *(uint2*)(Xh + r * LDH + (k4 >> 1)) = p;
    }
    for (int i = tid; i < 128 * 32; i += 256) {
        int r = i >> 5, k4 = (i & 31) << 2;
        float4 v = *(const float4*)(W + (size_t)r * DM + k4);
        uint2 p = make_uint2(pack_h2(v.x, v.y), pack_h2(v.z, v.w));
        *(uint2*)(Wh + r * LDH + (k4 >> 1)) = p;
    }
    __syncthreads();

    const uint32_t* abase = Xh + (mw * 32 + g) * LDH + q;
    const uint32_t* bbase = Wh + (nw * 32 + g) * LDH + q;

    float acc[2][4][4];
    #pragma unroll
    for (int t2 = 0; t2 < 2; t2++)
        #pragma unroll
        for (int j = 0; j < 4; j++)
            #pragma unroll
            for (int e = 0; e < 4; e++) acc[t2][j][e] = 0.f;

    #pragma unroll
    for (int ks = 0; ks < 8; ks++) {
        int k0 = ks * 8;
        uint32_t a[2][4];
        #pragma unroll
        for (int t2 = 0; t2 < 2; t2++) {
            const uint32_t* ap = abase + t2 * 16 * LDH + k0;
            a[t2][0] = ap[0];            a[t2][1] = ap[8 * LDH];
            a[t2][2] = ap[4];            a[t2][3] = ap[8 * LDH + 4];
        }
        #pragma unroll
        for (int j = 0; j < 4; j++) {
            const uint32_t* bp = bbase + j * 8 * LDH + k0;
            uint32_t b[2]; b[0] = bp[0]; b[1] = bp[4];
            mma16(acc[0][j], a[0], b);
            mma16(acc[1][j], a[1], b);
        }
    }
    __half* outh = &g_qkv[slot][row0][0];
    #pragma unroll
    for (int t2 = 0; t2 < 2; t2++) {
        int r = mw * 32 + t2 * 16 + g;
        #pragma unroll
        for (int j = 0; j < 4; j++) {
            int c = nw * 32 + j * 8 + q * 2;
            *(uint32_t*)(outh + (size_t)r * DM + c)       = pack_h2(acc[t2][j][0], acc[t2][j][1]);
            *(uint32_t*)(outh + (size_t)(r + 8) * DM + c) = pack_h2(acc[t2][j][2], acc[t2][j][3]);
        }
    }
}

// ===========================================================================
// Kernel 3: sparse-masked attention with fp16 K/V in SMEM, duplicated-row
// layout. Row stride = 32 uint32 (128B): 16 uint32 of half2 data + an exact
// duplicate at +16. Reader lane classes (lane&3 chunk-rotation) x (lane>>2&1
// copy-select) hit 8 disjoint 4-bank groups -> 4 phases per LDS.128, with
// HALF the loads of the fp32 layout (8 vs 16 per entry). fp32 math via cvt
// in-loop (bit-identical values to R11). Direct exp; fp16 output.
// ===========================================================================
__global__ void __launch_bounds__(512, 1)
attn_kernel() {
    extern __shared__ uint32_t smw[];
    uint32_t* Ks = smw;                // [512][32]: 16 data + 16 dup
    uint32_t* Vs = smw + 512 * 32;
    int tid = threadIdx.x;
    int h = blockIdx.x;
    int t = blockIdx.y >> 5, bp = blockIdx.y & 31;

    const __half* Kg = &g_qkv[t * 3 + 1][(size_t)bp * NN][0];
    const __half* Vg = &g_qkv[t * 3 + 2][(size_t)bp * NN][0];
    for (int i = tid; i < 512 * 4; i += 512) {
        int m = i >> 2, c = i & 3;
        uint4 kk = *(const uint4*)(Kg + (size_t)m * DM + h * DK + c * 8);
        *(uint4*)(Ks + m * 32 + c * 4)      = kk;
        *(uint4*)(Ks + m * 32 + 16 + c * 4) = kk;
        uint4 vv = *(const uint4*)(Vg + (size_t)m * DM + h * DK + c * 8);
        *(uint4*)(Vs + m * 32 + c * 4)      = vv;
        *(uint4*)(Vs + m * 32 + 16 + c * 4) = vv;
    }
    __syncthreads();

    int n = tid;
    int gn = bp * NN + n;
    int rot = tid & 3;
    int copyoff = ((tid >> 2) & 1) * 16;
    const float scale = 0.17677669529663687f;   // 1/sqrt(32), folded into Q

    // Q: 4 chunks of 8 dims, stored rotated: slot c = logical chunk (c+rot)&3
    float4 qa[4], qb[4];
    const __half* Qg = &g_qkv[t * 3 + 0][gn][h * DK];
    #pragma unroll
    for (int c = 0; c < 4; c++) {
        int cc = (c + rot) & 3;
        uint4 qv = *(const uint4*)(Qg + cc * 8);
        float2 f0 = __half22float2(*(__half2*)&qv.x);
        float2 f1 = __half22float2(*(__half2*)&qv.y);
        float2 f2 = __half22float2(*(__half2*)&qv.z);
        float2 f3 = __half22float2(*(__half2*)&qv.w);
        qa[c] = make_float4(f0.x * scale, f0.y * scale, f1.x * scale, f1.y * scale);
        qb[c] = make_float4(f2.x * scale, f2.y * scale, f3.x * scale, f3.y * scale);
    }
    int cnt = g_nnz[t][n];
    float Z = 0.f;
    float4 avA[4], avB[4];
    #pragma unroll
    for (int c = 0; c < 4; c++) {
        avA[c] = make_float4(0.f, 0.f, 0.f, 0.f);
        avB[c] = make_float4(0.f, 0.f, 0.f, 0.f);
    }

    for (int i = 0; i < cnt; i++) {
        int m = g_colsT[t][i][n];        // coalesced: lanes = consecutive n
        float tv = g_valsT[t][i][n];
        const uint32_t* kb = Ks + m * 32 + copyoff;
        float s = 0.f;
        #pragma unroll
        for (int c = 0; c < 4; c++) {
            uint4 kk = *(const uint4*)(kb + ((c + rot) & 3) * 4);
            float2 f0 = __half22float2(*(__half2*)&kk.x);
            float2 f1 = __half22float2(*(__half2*)&kk.y);
            float2 f2 = __half22float2(*(__half2*)&kk.z);
            float2 f3 = __half22float2(*(__half2*)&kk.w);
            s += qa[c].x * f0.x + qa[c].y * f0.y + qa[c].z * f1.x + qa[c].w * f1.y
               + qb[c].x * f2.x + qb[c].y * f2.y + qb[c].z * f3.x + qb[c].w * f3.y;
        }
        float e = __expf(s);
        Z += e;
        float we = tv * e;
        const uint32_t* vb = Vs + m * 32 + copyoff;
        #pragma unroll
        for (int c = 0; c < 4; c++) {
            uint4 vv = *(const uint4*)(vb + ((c + rot) & 3) * 4);
            float2 f0 = __half22float2(*(__half2*)&vv.x);
            float2 f1 = __half22float2(*(__half2*)&vv.y);
            float2 f2 = __half22float2(*(__half2*)&vv.z);
            float2 f3 = __half22float2(*(__half2*)&vv.w);
            avA[c].x += we * f0.x; avA[c].y += we * f0.y;
            avA[c].z += we * f1.x; avA[c].w += we * f1.y;
            avB[c].x += we * f2.x; avB[c].y += we * f2.y;
            avB[c].z += we * f3.x; avB[c].w += we * f3.y;
        }
    }
    float inv = 1.f / Z;
    __half* outh = &g_attn[t][gn][h * DK];
    #pragma unroll
    for (int c = 0; c < 4; c++) {
        int cc = (c + rot) & 3;
        uint4 p;
        p.x = pack_h2(avA[c].x * inv, avA[c].y * inv);
        p.y = pack_h2(avA[c].z * inv, avA[c].w * inv);
        p.z = pack_h2(avB[c].x * inv, avB[c].y * inv);
        p.w = pack_h2(avB[c].z * inv, avB[c].w * inv);
        *(uint4*)(outh + cc * 8) = p;
    }
}

// ===========================================================================
// Kernel 4: output projection via tf32 mma.sync (K=384 = 3 accumulated
// chunks), 512 threads / 16 warps; A staged from fp16 g_attn; fused
// residual + warp-per-row LayerNorm.
// ===========================================================================
__global__ void __launch_bounds__(512, 1)
outproj_mma_kernel(const float* __restrict__ X,
                   const float* __restrict__ Wo,
                   const float* __restrict__ gamma,
                   const float* __restrict__ beta,
                   float* __restrict__ out) {
    extern __shared__ uint32_t sm[];
    uint32_t* As = sm;                 // [128][LDP]
    uint32_t* Ws = sm + 128 * LDP;     // [128][LDP]
    float* Ys = (float*)sm;            // reuse As after GEMM
    int tid = threadIdx.x, lane = tid & 31, wid = tid >> 5;
    int mw = wid & 3, nw = wid >> 2;
    int g = lane >> 2, q = lane & 3;
    int row0 = blockIdx.x * 128;

    const uint32_t* abase = As + (mw * 32 + g) * LDP + q;
    const uint32_t* bbase = Ws + (nw * 32 + g) * LDP + q;

    float acc[2][4][4];
    #pragma unroll
    for (int t2 = 0; t2 < 2; t2++)
        #pragma unroll
        for (int j = 0; j < 4; j++)
            #pragma unroll
            for (int e = 0; e < 4; e++) acc[t2][j][e] = 0.f;

    for (int t = 0; t < NT; t++) {
        __syncthreads();
        for (int i = tid; i < 128 * 16; i += 512) {
            int r = i >> 4, k = (i & 15) << 3;
            uint4 a = *(const uint4*)(&g_attn[t][row0 + r][k]);
            float2 f0 = __half22float2(*(__half2*)&a.x);
            float2 f1 = __half22float2(*(__half2*)&a.y);
            float2 f2 = __half22float2(*(__half2*)&a.z);
            float2 f3 = __half22float2(*(__half2*)&a.w);
            uint32_t* d = As + r * LDP + k;
            d[0] = f2tf32(f0.x); d[1] = f2tf32(f0.y);
            d[2] = f2tf32(f1.x); d[3] = f2tf32(f1.y);
            d[4] = f2tf32(f2.x); d[5] = f2tf32(f2.y);
            d[6] = f2tf32(f3.x); d[7] = f2tf32(f3.y);
        }
        for (int i = tid; i < 128 * 32; i += 512) {
            int r = i >> 5, k = (i & 31) << 2;
            float4 w = *(const float4*)(Wo + (size_t)r * (NT * DM) + t * DM + k);
            uint32_t* d2 = Ws + r * LDP + k;
            d2[0] = f2tf32(w.x); d2[1] = f2tf32(w.y); d2[2] = f2tf32(w.z); d2[3] = f2tf32(w.w);
        }
        __syncthreads();
        #pragma unroll 4
        for (int ks = 0; ks < 16; ks++) {
            int k0 = ks * 8;
            uint32_t a[2][4];
            #pragma unroll
            for (int t2 = 0; t2 < 2; t2++) {
                const uint32_t* ap = abase + t2 * 16 * LDP + k0;
                a[t2][0] = ap[0]; a[t2][1] = ap[8 * LDP];
                a[t2][2] = ap[4]; a[t2][3] = ap[8 * LDP + 4];
            }
            #pragma unroll
            for (int j = 0; j < 4; j++) {
                const uint32_t* bp = bbase + j * 8 * LDP + k0;
                uint32_t b[2]; b[0] = bp[0]; b[1] = bp[4];
                mma8(acc[0][j], a[0], b);
                mma8(acc[1][j], a[1], b);
            }
        }
    }
    __syncthreads();
    #pragma unroll
    for (int t2 = 0; t2 < 2; t2++) {
        int r = mw * 32 + t2 * 16 + g;
        #pragma unroll
        for (int j = 0; j < 4; j++) {
            int c = nw * 32 + j * 8 + q * 2;
            *(float2*)(Ys + r * LDP + c)       = make_float2(acc[t2][j][0], acc[t2][j][1]);
            *(float2*)(Ys + (r + 8) * LDP + c) = make_float2(acc[t2][j][2], acc[t2][j][3]);
        }
    }
    __syncthreads();
    for (int r = wid; r < 128; r += 16) {
        float4 y  = *(float4*)(Ys + r * LDP + lane * 4);
        float4 xv = *(const float4*)(X + (size_t)(row0 + r) * DM + lane * 4);
        float v0 = y.x + xv.x, v1 = y.y + xv.y, v2 = y.z + xv.z, v3 = y.w + xv.w;
        float s  = v0 + v1 + v2 + v3;
        float s2 = v0 * v0 + v1 * v1 + v2 * v2 + v3 * v3;
        #pragma unroll
        for (int off = 16; off; off >>= 1) {
            s  += __shfl_xor_sync(0xffffffffu, s,  off);
            s2 += __shfl_xor_sync(0xffffffffu, s2, off);
        }
        float mu = s * (1.f / DM);
        float var = s2 * (1.f / DM) - mu * mu;
        float rs = rsqrtf(var + 1e-5f);
        float4 gv = *(const float4*)(gamma + lane * 4);
        float4 bv = *(const float4*)(beta + lane * 4);
        float4 res = make_float4((v0 - mu) * rs * gv.x + bv.x,
                                 (v1 - mu) * rs * gv.y + bv.y,
                                 (v2 - mu) * rs * gv.z + bv.z,
                                 (v3 - mu) * rs * gv.w + bv.w);
        *(float4*)(out + (size_t)(row0 + r) * DM + lane * 4) = res;
    }
}

// ===========================================================================
extern "C" void kernel_launch(void* const* d_in, const int* in_sizes, int n_in,
                              void* d_out, int out_size) {
    const float* inputs = (const float*)d_in[0];
    const float* tm     = (const float*)d_in[2];
    const float* Wq     = (const float*)d_in[3];
    const float* Wk     = (const float*)d_in[4];
    const float* Wv     = (const float*)d_in[5];
    const float* Wo     = (const float*)d_in[6];
    const float* gamma  = (const float*)d_in[7];
    const float* beta   = (const float*)d_in[8];
    float* out = (float*)d_out;

    int smem_qkv  = (64 + 128) * LDH * (int)sizeof(uint32_t); // 52224
    int smem_attn = 2 * 512 * 32 * (int)sizeof(uint32_t);     // 131072
    int smem_out  = 2 * 128 * LDP * (int)sizeof(float);       // 135168
    cudaFuncSetAttribute(qkv_mma_kernel,     cudaFuncAttributeMaxDynamicSharedMemorySize, smem_qkv);
    cudaFuncSetAttribute(attn_kernel,        cudaFuncAttributeMaxDynamicSharedMemorySize, smem_attn);
    cudaFuncSetAttribute(outproj_mma_kernel, cudaFuncAttributeMaxDynamicSharedMemorySize, smem_out);

    build_csr_kernel<<<(NT * NN * 32 + 255) / 256, 256>>>(tm);
    qkv_mma_kernel<<<dim3(NROWS / 64, 9), 256, smem_qkv>>>(inputs, Wq, Wk, Wv);
    attn_kernel<<<dim3(NH, NT * NB * NP), 512, smem_attn>>>();
    outproj_mma_kernel<<<NROWS / 128, 512, smem_out>>>(inputs, Wo, gamma, beta, out);
}

// round 14
// speedup vs baseline: 1.2226x; 1.0934x over previous
#include <cuda_runtime.h>
#include <cuda_fp16.h>
#include <math.h>
#include <stdint.h>

#define NB 4
#define NP 8
#define NN 512
#define DM 128
#define NH 4
#define DK 32
#define NT 3
#define NROWS (NB*NP*NN)     // 16384
#define MAXNNZ 128
#define LISTD 132
#define LDP 132              // smem row stride (floats) for fp32 epilogue scratch
#define LDH 68               // smem row stride (uint32 = half2) for fp16 tiles

// Scratch (device globals). fp16 intermediates to halve HBM traffic.
__device__ __half g_Xh[NROWS][DM];       // inputs pre-converted to fp16
__device__ __half g_Wh[9][DM][DM];       // Wq/Wk/Wv pre-converted to fp16
__device__ __half g_qkv[9][NROWS][DM];   // [t*3 + {Q,K,V}][row][d]
__device__ __half g_attn[NT][NROWS][DM]; // per-t attention output (fp16)
__device__ int    g_nnz[NT][NN];
__device__ int    g_colsT[NT][LISTD][NN];   // [t][i][n] -> coalesced over n
__device__ float  g_valsT[NT][LISTD][NN];

__constant__ int c_which[NT] = {0, 1, 3};

// ---------------------------------------------------------------------------
__device__ __forceinline__ uint32_t pack_h2(float a, float b) {
    __half2 h = __floats2half2_rn(a, b);
    return *(uint32_t*)&h;
}
// m16n8k16 fp16 MMA, fp32 accum, D += A*B (row x col)
__device__ __forceinline__ void mma16(float d[4], const uint32_t a[4], const uint32_t b[2]) {
    asm volatile("mma.sync.aligned.m16n8k16.row.col.f32.f16.f16.f32 "
        "{%0,%1,%2,%3}, {%4,%5,%6,%7}, {%8,%9}, {%0,%1,%2,%3};"
        : "+f"(d[0]), "+f"(d[1]), "+f"(d[2]), "+f"(d[3])
        : "r"(a[0]), "r"(a[1]), "r"(a[2]), "r"(a[3]), "r"(b[0]), "r"(b[1]));
}

// ===========================================================================
// Kernel 0: pre-convert X (16384x128) and the 9 weight slots to fp16.
// ===========================================================================
#define XV (NROWS*DM/8)      // 262144 8-elem vectors
#define WV (9*DM*DM/8)       // 18432
__global__ void convert_kernel(const float* __restrict__ X,
                               const float* __restrict__ Wq,
                               const float* __restrict__ Wk,
                               const float* __restrict__ Wv) {
    int idx = blockIdx.x * blockDim.x + threadIdx.x;
    if (idx < XV) {
        const float4* s = (const float4*)X + (size_t)idx * 2;
        float4 a = s[0], b = s[1];
        uint4 p = make_uint4(pack_h2(a.x, a.y), pack_h2(a.z, a.w),
                             pack_h2(b.x, b.y), pack_h2(b.z, b.w));
        *(uint4*)(&g_Xh[0][0] + (size_t)idx * 8) = p;
    } else if (idx < XV + WV) {
        int w = idx - XV;
        int slot = w / (DM * DM / 8);
        int off  = w % (DM * DM / 8);
        const float* Wb3[3] = {Wq, Wk, Wv};
        const float4* s = (const float4*)(Wb3[slot % 3] + (size_t)(slot / 3) * DM * DM) + (size_t)off * 2;
        float4 a = s[0], b = s[1];
        uint4 p = make_uint4(pack_h2(a.x, a.y), pack_h2(a.z, a.w),
                             pack_h2(b.x, b.y), pack_h2(b.z, b.w));
        *(uint4*)(&g_Wh[slot][0][0] + (size_t)off * 8) = p;
    }
}

// ===========================================================================
// Kernel 1: build transposed CSR of the selected transition matrices.
// ===========================================================================
__global__ void build_csr_kernel(const float* __restrict__ tmall) {
    int wg   = (blockIdx.x * blockDim.x + threadIdx.x) >> 5;
    int lane = threadIdx.x & 31;
    if (wg >= NT * NN) return;
    int t = wg / NN, n = wg % NN;
    const float* row = tmall + ((size_t)c_which[t] * NN + n) * NN;
    int cnt = 0;
    for (int base = 0; base < NN; base += 32) {
        float v = row[base + lane];
        unsigned b = __ballot_sync(0xffffffffu, v != 0.0f);
        if (v != 0.0f) {
            int pos = cnt + __popc(b & ((1u << lane) - 1u));
            if (pos < MAXNNZ) { g_colsT[t][pos][n] = base + lane; g_valsT[t][pos][n] = v; }
        }
        cnt += __popc(b);
    }
    if (lane == 0) g_nnz[t][n] = cnt < MAXNNZ ? cnt : MAXNNZ;
}

// ===========================================================================
// Kernel 2: QKV projections via fp16 mma.sync m16n8k16 (fp32 accumulate).
// grid = (256 tiles, 9 slots); 256 threads / 8 warps; 3 CTAs/SM.
// Stages pre-converted fp16 X/W (pure uint4 copies, no cvt). fp16 out.
// ===========================================================================
__global__ void __launch_bounds__(256, 3)
qkv_mma_kernel() {
    extern __shared__ uint32_t sm[];
    uint32_t* Xh = sm;                // [64][LDH] half2 units
    uint32_t* Wh = sm + 64 * LDH;     // [128][LDH]
    int tid = threadIdx.x, lane = tid & 31, wid = tid >> 5;
    int mw = wid & 1, nw = wid >> 1;
    int g = lane >> 2, q = lane & 3;
    int slot = blockIdx.y;
    int row0 = blockIdx.x * 64;

    const __half* Xg = &g_Xh[row0][0];
    for (int i = tid; i < 64 * 16; i += 256) {
        int r = i >> 4, c = i & 15;
        uint4 v = *(const uint4*)(Xg + (size_t)r * DM + c * 8);
        *(uint4*)(Xh + r * LDH + c * 4) = v;
    }
    const __half* Wg = &g_Wh[slot][0][0];
    for (int i = tid; i < 128 * 16; i += 256) {
        int r = i >> 4, c = i & 15;
        uint4 v = *(const uint4*)(Wg + (size_t)r * DM + c * 8);
        *(uint4*)(Wh + r * LDH + c * 4) = v;
    }
    __syncthreads();

    const uint32_t* abase = Xh + (mw * 32 + g) * LDH + q;
    const uint32_t* bbase = Wh + (nw * 32 + g) * LDH + q;

    float acc[2][4][4];
    #pragma unroll
    for (int t2 = 0; t2 < 2; t2++)
        #pragma unroll
        for (int j = 0; j < 4; j++)
            #pragma unroll
            for (int e = 0; e < 4; e++) acc[t2][j][e] = 0.f;

    #pragma unroll
    for (int ks = 0; ks < 8; ks++) {
        int k0 = ks * 8;
        uint32_t a[2][4];
        #pragma unroll
        for (int t2 = 0; t2 < 2; t2++) {
            const uint32_t* ap = abase + t2 * 16 * LDH + k0;
            a[t2][0] = ap[0];            a[t2][1] = ap[8 * LDH];
            a[t2][2] = ap[4];            a[t2][3] = ap[8 * LDH + 4];
        }
        #pragma unroll
        for (int j = 0; j < 4; j++) {
            const uint32_t* bp = bbase + j * 8 * LDH + k0;
            uint32_t b[2]; b[0] = bp[0]; b[1] = bp[4];
            mma16(acc[0][j], a[0], b);
            mma16(acc[1][j], a[1], b);
        }
    }
    __half* outh = &g_qkv[slot][row0][0];
    #pragma unroll
    for (int t2 = 0; t2 < 2; t2++) {
        int r = mw * 32 + t2 * 16 + g;
        #pragma unroll
        for (int j = 0; j < 4; j++) {
            int c = nw * 32 + j * 8 + q * 2;
            *(uint32_t*)(outh + (size_t)r * DM + c)       = pack_h2(acc[t2][j][0], acc[t2][j][1]);
            *(uint32_t*)(outh + (size_t)(r + 8) * DM + c) = pack_h2(acc[t2][j][2], acc[t2][j][3]);
        }
    }
}

// ===========================================================================
// Kernel 3: sparse-masked attention (R13 structure, unchanged). fp16 K/V in
// SMEM with duplicated-row layout (128B stride, data + duplicate at +64B);
// (lane&3 rotation) x (lane>>2&1 copy-select) -> 4-phase LDS.128, 8 loads
// per entry. fp32 math via in-loop cvt. Direct exp; fp16 output.
// ===========================================================================
__global__ void __launch_bounds__(512, 1)
attn_kernel() {
    extern __shared__ uint32_t smw[];
    uint32_t* Ks = smw;                // [512][32]: 16 data + 16 dup
    uint32_t* Vs = smw + 512 * 32;
    int tid = threadIdx.x;
    int h = blockIdx.x;
    int t = blockIdx.y >> 5, bp = blockIdx.y & 31;

    const __half* Kg = &g_qkv[t * 3 + 1][(size_t)bp * NN][0];
    const __half* Vg = &g_qkv[t * 3 + 2][(size_t)bp * NN][0];
    for (int i = tid; i < 512 * 4; i += 512) {
        int m = i >> 2, c = i & 3;
        uint4 kk = *(const uint4*)(Kg + (size_t)m * DM + h * DK + c * 8);
        *(uint4*)(Ks + m * 32 + c * 4)      = kk;
        *(uint4*)(Ks + m * 32 + 16 + c * 4) = kk;
        uint4 vv = *(const uint4*)(Vg + (size_t)m * DM + h * DK + c * 8);
        *(uint4*)(Vs + m * 32 + c * 4)      = vv;
        *(uint4*)(Vs + m * 32 + 16 + c * 4) = vv;
    }
    __syncthreads();

    int n = tid;
    int gn = bp * NN + n;
    int rot = tid & 3;
    int copyoff = ((tid >> 2) & 1) * 16;
    const float scale = 0.17677669529663687f;   // 1/sqrt(32), folded into Q

    float4 qa[4], qb[4];
    const __half* Qg = &g_qkv[t * 3 + 0][gn][h * DK];
    #pragma unroll
    for (int c = 0; c < 4; c++) {
        int cc = (c + rot) & 3;
        uint4 qv = *(const uint4*)(Qg + cc * 8);
        float2 f0 = __half22float2(*(__half2*)&qv.x);
        float2 f1 = __half22float2(*(__half2*)&qv.y);
        float2 f2 = __half22float2(*(__half2*)&qv.z);
        float2 f3 = __half22float2(*(__half2*)&qv.w);
        qa[c] = make_float4(f0.x * scale, f0.y * scale, f1.x * scale, f1.y * scale);
        qb[c] = make_float4(f2.x * scale, f2.y * scale, f3.x * scale, f3.y * scale);
    }
    int cnt = g_nnz[t][n];
    float Z = 0.f;
    float4 avA[4], avB[4];
    #pragma unroll
    for (int c = 0; c < 4; c++) {
        avA[c] = make_float4(0.f, 0.f, 0.f, 0.f);
        avB[c] = make_float4(0.f, 0.f, 0.f, 0.f);
    }

    for (int i = 0; i < cnt; i++) {
        int m = g_colsT[t][i][n];        // coalesced: lanes = consecutive n
        float tv = g_valsT[t][i][n];
        const uint32_t* kb = Ks + m * 32 + copyoff;
        float s = 0.f;
        #pragma unroll
        for (int c = 0; c < 4; c++) {
            uint4 kk = *(const uint4*)(kb + ((c + rot) & 3) * 4);
            float2 f0 = __half22float2(*(__half2*)&kk.x);
            float2 f1 = __half22float2(*(__half2*)&kk.y);
            float2 f2 = __half22float2(*(__half2*)&kk.z);
            float2 f3 = __half22float2(*(__half2*)&kk.w);
            s += qa[c].x * f0.x + qa[c].y * f0.y + qa[c].z * f1.x + qa[c].w * f1.y
               + qb[c].x * f2.x + qb[c].y * f2.y + qb[c].z * f3.x + qb[c].w * f3.y;
        }
        float e = __expf(s);
        Z += e;
        float we = tv * e;
        const uint32_t* vb = Vs + m * 32 + copyoff;
        #pragma unroll
        for (int c = 0; c < 4; c++) {
            uint4 vv = *(const uint4*)(vb + ((c + rot) & 3) * 4);
            float2 f0 = __half22float2(*(__half2*)&vv.x);
            float2 f1 = __half22float2(*(__half2*)&vv.y);
            float2 f2 = __half22float2(*(__half2*)&vv.z);
            float2 f3 = __half22float2(*(__half2*)&vv.w);
            avA[c].x += we * f0.x; avA[c].y += we * f0.y;
            avA[c].z += we * f1.x; avA[c].w += we * f1.y;
            avB[c].x += we * f2.x; avB[c].y += we * f2.y;
            avB[c].z += we * f3.x; avB[c].w += we * f3.y;
        }
    }
    float inv = 1.f / Z;
    __half* outh = &g_attn[t][gn][h * DK];
    #pragma unroll
    for (int c = 0; c < 4; c++) {
        int cc = (c + rot) & 3;
        uint4 p;
        p.x = pack_h2(avA[c].x * inv, avA[c].y * inv);
        p.y = pack_h2(avA[c].z * inv, avA[c].w * inv);
        p.z = pack_h2(avB[c].x * inv, avB[c].y * inv);
        p.w = pack_h2(avB[c].z * inv, avB[c].w * inv);
        *(uint4*)(outh + cc * 8) = p;
    }
}

// ===========================================================================
// Kernel 4: output projection via fp16 mma.sync m16n8k16 (K=384 = 3
// accumulated chunks), 512 threads / 16 warps; A = fp16 g_attn staged as
// raw uint4 copies; Wo packed fp32->fp16. Fused residual + warp-per-row LN.
// ===========================================================================
__global__ void __launch_bounds__(512, 1)
outproj_mma_kernel(const float* __restrict__ X,
                   const float* __restrict__ Wo,
                   const float* __restrict__ gamma,
                   const float* __restrict__ beta,
                   float* __restrict__ out) {
    extern __shared__ uint32_t sm[];
    uint32_t* As = sm;                 // [128][LDH]
    uint32_t* Ws = sm + 128 * LDH;     // [128][LDH]
    float* Ys = (float*)sm;            // reuse (LDP stride) after GEMM
    int tid = threadIdx.x, lane = tid & 31, wid = tid >> 5;
    int mw = wid & 3, nw = wid >> 2;
    int g = lane >> 2, q = lane & 3;
    int row0 = blockIdx.x * 128;

    const uint32_t* abase = As + (mw * 32 + g) * LDH + q;
    const uint32_t* bbase = Ws + (nw * 32 + g) * LDH + q;

    float acc[2][4][4];
    #pragma unroll
    for (int t2 = 0; t2 < 2; t2++)
        #pragma unroll
        for (int j = 0; j < 4; j++)
            #pragma unroll
            for (int e = 0; e < 4; e++) acc[t2][j][e] = 0.f;

    for (int t = 0; t < NT; t++) {
        __syncthreads();
        // A from fp16 g_attn: raw uint4 copy (no cvt)
        for (int i = tid; i < 128 * 16; i += 512) {
            int r = i >> 4, c = i & 15;
            uint4 a = *(const uint4*)(&g_attn[t][row0 + r][c * 8]);
            *(uint4*)(As + r * LDH + c * 4) = a;
        }
        // W: Wo fp32 -> fp16 pack
        for (int i = tid; i < 128 * 32; i += 512) {
            int r = i >> 5, k4 = (i & 31) << 2;
            float4 w = *(const float4*)(Wo + (size_t)r * (NT * DM) + t * DM + k4);
            uint2 p = make_uint2(pack_h2(w.x, w.y), pack_h2(w.z, w.w));
            *(uint2*)(Ws + r * LDH + (k4 >> 1)) = p;
        }
        __syncthreads();
        #pragma unroll
        for (int ks = 0; ks < 8; ks++) {
            int k0 = ks * 8;
            uint32_t a[2][4];
            #pragma unroll
            for (int t2 = 0; t2 < 2; t2++) {
                const uint32_t* ap = abase + t2 * 16 * LDH + k0;
                a[t2][0] = ap[0];            a[t2][1] = ap[8 * LDH];
                a[t2][2] = ap[4];            a[t2][3] = ap[8 * LDH + 4];
            }
            #pragma unroll
            for (int j = 0; j < 4; j++) {
                const uint32_t* bp = bbase + j * 8 * LDH + k0;
                uint32_t b[2]; b[0] = bp[0]; b[1] = bp[4];
                mma16(acc[0][j], a[0], b);
                mma16(acc[1][j], a[1], b);
            }
        }
    }
    __syncthreads();
    #pragma unroll
    for (int t2 = 0; t2 < 2; t2++) {
        int r = mw * 32 + t2 * 16 + g;
        #pragma unroll
        for (int j = 0; j < 4; j++) {
            int c = nw * 32 + j * 8 + q * 2;
            *(float2*)(Ys + r * LDP + c)       = make_float2(acc[t2][j][0], acc[t2][j][1]);
            *(float2*)(Ys + (r + 8) * LDP + c) = make_float2(acc[t2][j][2], acc[t2][j][3]);
        }
    }
    __syncthreads();
    for (int r = wid; r < 128; r += 16) {
        float4 y  = *(float4*)(Ys + r * LDP + lane * 4);
        float4 xv = *(const float4*)(X + (size_t)(row0 + r) * DM + lane * 4);
        float v0 = y.x + xv.x, v1 = y.y + xv.y, v2 = y.z + xv.z, v3 = y.w + xv.w;
        float s  = v0 + v1 + v2 + v3;
        float s2 = v0 * v0 + v1 * v1 + v2 * v2 + v3 * v3;
        #pragma unroll
        for (int off = 16; off; off >>= 1) {
            s  += __shfl_xor_sync(0xffffffffu, s,  off);
            s2 += __shfl_xor_sync(0xffffffffu, s2, off);
        }
        float mu = s * (1.f / DM);
        float var = s2 * (1.f / DM) - mu * mu;
        float rs = rsqrtf(var + 1e-5f);
        float4 gv = *(const float4*)(gamma + lane * 4);
        float4 bv = *(const float4*)(beta + lane * 4);
        float4 res = make_float4((v0 - mu) * rs * gv.x + bv.x,
                                 (v1 - mu) * rs * gv.y + bv.y,
                                 (v2 - mu) * rs * gv.z + bv.z,
                                 (v3 - mu) * rs * gv.w + bv.w);
        *(float4*)(out + (size_t)(row0 + r) * DM + lane * 4) = res;
    }
}

// ===========================================================================
extern "C" void kernel_launch(void* const* d_in, const int* in_sizes, int n_in,
                              void* d_out, int out_size) {
    const float* inputs = (const float*)d_in[0];
    const float* tm     = (const float*)d_in[2];
    const float* Wq     = (const float*)d_in[3];
    const float* Wk     = (const float*)d_in[4];
    const float* Wv     = (const float*)d_in[5];
    const float* Wo     = (const float*)d_in[6];
    const float* gamma  = (const float*)d_in[7];
    const float* beta   = (const float*)d_in[8];
    float* out = (float*)d_out;

    int smem_qkv  = (64 + 128) * LDH * (int)sizeof(uint32_t); // 52224
    int smem_attn = 2 * 512 * 32 * (int)sizeof(uint32_t);     // 131072
    int smem_out  = 2 * 128 * LDH * (int)sizeof(uint32_t);    // 69632
    if (smem_out < 128 * LDP * (int)sizeof(float)) smem_out = 128 * LDP * (int)sizeof(float);
    cudaFuncSetAttribute(qkv_mma_kernel,     cudaFuncAttributeMaxDynamicSharedMemorySize, smem_qkv);
    cudaFuncSetAttribute(attn_kernel,        cudaFuncAttributeMaxDynamicSharedMemorySize, smem_attn);
    cudaFuncSetAttribute(outproj_mma_kernel, cudaFuncAttributeMaxDynamicSharedMemorySize, smem_out);

    convert_kernel<<<(XV + WV + 255) / 256, 256>>>(inputs, Wq, Wk, Wv);
    build_csr_kernel<<<(NT * NN * 32 + 255) / 256, 256>>>(tm);
    qkv_mma_kernel<<<dim3(NROWS / 64, 9), 256, smem_qkv>>>();
    attn_kernel<<<dim3(NH, NT * NB * NP), 512, smem_attn>>>();
    outproj_mma_kernel<<<NROWS / 128, 512, smem_out>>>(inputs, Wo, gamma, beta, out);
}

// round 15
// speedup vs baseline: 1.2874x; 1.0530x over previous
#include <cuda_runtime.h>
#include <cuda_fp16.h>
#include <math.h>
#include <stdint.h>

#define NB 4
#define NP 8
#define NN 512
#define DM 128
#define NH 4
#define DK 32
#define NT 3
#define NROWS (NB*NP*NN)     // 16384
#define MAXNNZ 128
#define LISTD 132
#define LDP 132              // smem row stride (floats) for fp32 epilogue scratch
#define LDH 68               // smem row stride (uint32 = half2) for fp16 tiles

// Scratch (device globals). fp16 intermediates to halve HBM traffic.
__device__ __half g_Xh[NROWS][DM];       // inputs pre-converted to fp16
__device__ __half g_Wh[9][DM][DM];       // Wq/Wk/Wv pre-converted to fp16
__device__ __half g_qkv[9][NROWS][DM];   // [t*3 + {Q,K,V}][row][d]
__device__ __half g_attn[NT][NROWS][DM]; // per-t attention output (fp16)
__device__ int    g_nnz[NT][NN];
__device__ int    g_colsT[NT][LISTD][NN];   // [t][i][n] -> coalesced over n
__device__ float  g_valsT[NT][LISTD][NN];

__constant__ int c_which[NT] = {0, 1, 3};

// ---------------------------------------------------------------------------
__device__ __forceinline__ uint32_t pack_h2(float a, float b) {
    __half2 h = __floats2half2_rn(a, b);
    return *(uint32_t*)&h;
}
__device__ __forceinline__ __half2 u2h2(uint32_t u) { return *(__half2*)&u; }
// m16n8k16 fp16 MMA, fp32 accum, D += A*B (row x col)
__device__ __forceinline__ void mma16(float d[4], const uint32_t a[4], const uint32_t b[2]) {
    asm volatile("mma.sync.aligned.m16n8k16.row.col.f32.f16.f16.f32 "
        "{%0,%1,%2,%3}, {%4,%5,%6,%7}, {%8,%9}, {%0,%1,%2,%3};"
        : "+f"(d[0]), "+f"(d[1]), "+f"(d[2]), "+f"(d[3])
        : "r"(a[0]), "r"(a[1]), "r"(a[2]), "r"(a[3]), "r"(b[0]), "r"(b[1]));
}

// ===========================================================================
// Kernel 0: pre-convert X (16384x128) and the 9 weight slots to fp16.
// ===========================================================================
#define XV (NROWS*DM/8)      // 262144 8-elem vectors
#define WV (9*DM*DM/8)       // 18432
__global__ void convert_kernel(const float* __restrict__ X,
                               const float* __restrict__ Wq,
                               const float* __restrict__ Wk,
                               const float* __restrict__ Wv) {
    int idx = blockIdx.x * blockDim.x + threadIdx.x;
    if (idx < XV) {
        const float4* s = (const float4*)X + (size_t)idx * 2;
        float4 a = s[0], b = s[1];
        uint4 p = make_uint4(pack_h2(a.x, a.y), pack_h2(a.z, a.w),
                             pack_h2(b.x, b.y), pack_h2(b.z, b.w));
        *(uint4*)(&g_Xh[0][0] + (size_t)idx * 8) = p;
    } else if (idx < XV + WV) {
        int w = idx - XV;
        int slot = w / (DM * DM / 8);
        int off  = w % (DM * DM / 8);
        const float* Wb3[3] = {Wq, Wk, Wv};
        const float4* s = (const float4*)(Wb3[slot % 3] + (size_t)(slot / 3) * DM * DM) + (size_t)off * 2;
        float4 a = s[0], b = s[1];
        uint4 p = make_uint4(pack_h2(a.x, a.y), pack_h2(a.z, a.w),
                             pack_h2(b.x, b.y), pack_h2(b.z, b.w));
        *(uint4*)(&g_Wh[slot][0][0] + (size_t)off * 8) = p;
    }
}

// ===========================================================================
// Kernel 1: build transposed CSR of the selected transition matrices.
// ===========================================================================
__global__ void build_csr_kernel(const float* __restrict__ tmall) {
    int wg   = (blockIdx.x * blockDim.x + threadIdx.x) >> 5;
    int lane = threadIdx.x & 31;
    if (wg >= NT * NN) return;
    int t = wg / NN, n = wg % NN;
    const float* row = tmall + ((size_t)c_which[t] * NN + n) * NN;
    int cnt = 0;
    for (int base = 0; base < NN; base += 32) {
        float v = row[base + lane];
        unsigned b = __ballot_sync(0xffffffffu, v != 0.0f);
        if (v != 0.0f) {
            int pos = cnt + __popc(b & ((1u << lane) - 1u));
            if (pos < MAXNNZ) { g_colsT[t][pos][n] = base + lane; g_valsT[t][pos][n] = v; }
        }
        cnt += __popc(b);
    }
    if (lane == 0) g_nnz[t][n] = cnt < MAXNNZ ? cnt : MAXNNZ;
}

// ===========================================================================
// Kernel 2: QKV projections via fp16 mma.sync m16n8k16 (fp32 accumulate).
// grid = (256 tiles, 9 slots); 256 threads / 8 warps; 3 CTAs/SM.
// ===========================================================================
__global__ void __launch_bounds__(256, 3)
qkv_mma_kernel() {
    extern __shared__ uint32_t sm[];
    uint32_t* Xh = sm;                // [64][LDH]
    uint32_t* Wh = sm + 64 * LDH;     // [128][LDH]
    int tid = threadIdx.x, lane = tid & 31, wid = tid >> 5;
    int mw = wid & 1, nw = wid >> 1;
    int g = lane >> 2, q = lane & 3;
    int slot = blockIdx.y;
    int row0 = blockIdx.x * 64;

    const __half* Xg = &g_Xh[row0][0];
    for (int i = tid; i < 64 * 16; i += 256) {
        int r = i >> 4, c = i & 15;
        uint4 v = *(const uint4*)(Xg + (size_t)r * DM + c * 8);
        *(uint4*)(Xh + r * LDH + c * 4) = v;
    }
    const __half* Wg = &g_Wh[slot][0][0];
    for (int i = tid; i < 128 * 16; i += 256) {
        int r = i >> 4, c = i & 15;
        uint4 v = *(const uint4*)(Wg + (size_t)r * DM + c * 8);
        *(uint4*)(Wh + r * LDH + c * 4) = v;
    }
    __syncthreads();

    const uint32_t* abase = Xh + (mw * 32 + g) * LDH + q;
    const uint32_t* bbase = Wh + (nw * 32 + g) * LDH + q;

    float acc[2][4][4];
    #pragma unroll
    for (int t2 = 0; t2 < 2; t2++)
        #pragma unroll
        for (int j = 0; j < 4; j++)
            #pragma unroll
            for (int e = 0; e < 4; e++) acc[t2][j][e] = 0.f;

    #pragma unroll
    for (int ks = 0; ks < 8; ks++) {
        int k0 = ks * 8;
        uint32_t a[2][4];
        #pragma unroll
        for (int t2 = 0; t2 < 2; t2++) {
            const uint32_t* ap = abase + t2 * 16 * LDH + k0;
            a[t2][0] = ap[0];            a[t2][1] = ap[8 * LDH];
            a[t2][2] = ap[4];            a[t2][3] = ap[8 * LDH + 4];
        }
        #pragma unroll
        for (int j = 0; j < 4; j++) {
            const uint32_t* bp = bbase + j * 8 * LDH + k0;
            uint32_t b[2]; b[0] = bp[0]; b[1] = bp[4];
            mma16(acc[0][j], a[0], b);
            mma16(acc[1][j], a[1], b);
        }
    }
    __half* outh = &g_qkv[slot][row0][0];
    #pragma unroll
    for (int t2 = 0; t2 < 2; t2++) {
        int r = mw * 32 + t2 * 16 + g;
        #pragma unroll
        for (int j = 0; j < 4; j++) {
            int c = nw * 32 + j * 8 + q * 2;
            *(uint32_t*)(outh + (size_t)r * DM + c)       = pack_h2(acc[t2][j][0], acc[t2][j][1]);
            *(uint32_t*)(outh + (size_t)(r + 8) * DM + c) = pack_h2(acc[t2][j][2], acc[t2][j][3]);
        }
    }
}

// ===========================================================================
// Kernel 3: sparse-masked attention, issue-optimized inner loop:
//  - K in fp16 SMEM, duplicated-row layout (4 LDS.128/entry, 4-phase);
//    dot via 16 HFMA2 in 4 parallel chains, combined in fp32 (no per-element
//    cvt for K).
//  - V in fp32 SMEM, R4 rotated layout (8 LDS.128/entry, 4-phase);
//    accumulation in full fp32 FFMA (no cvt -- conversion done at staging).
// ~90 inst/iter vs 145 in the all-fp16-SMEM version. fp16 output.
// ===========================================================================
__global__ void __launch_bounds__(512, 1)
attn_kernel() {
    extern __shared__ uint32_t smw[];
    uint32_t* Ks = smw;                 // [512][32] uint32: 16 data + 16 dup
    float*    Vs = (float*)(smw + 512 * 32);  // [512][32] fp32
    int tid = threadIdx.x;
    int h = blockIdx.x;
    int t = blockIdx.y >> 5, bp = blockIdx.y & 31;

    const __half* Kg = &g_qkv[t * 3 + 1][(size_t)bp * NN][0];
    const __half* Vg = &g_qkv[t * 3 + 2][(size_t)bp * NN][0];
    for (int i = tid; i < 512 * 4; i += 512) {
        int m = i >> 2, c = i & 3;
        uint4 kk = *(const uint4*)(Kg + (size_t)m * DM + h * DK + c * 8);
        *(uint4*)(Ks + m * 32 + c * 4)      = kk;
        *(uint4*)(Ks + m * 32 + 16 + c * 4) = kk;
        uint4 vv = *(const uint4*)(Vg + (size_t)m * DM + h * DK + c * 8);
        float2 f0 = __half22float2(u2h2(vv.x));
        float2 f1 = __half22float2(u2h2(vv.y));
        float2 f2 = __half22float2(u2h2(vv.z));
        float2 f3 = __half22float2(u2h2(vv.w));
        *(float4*)(Vs + m * 32 + c * 8)     = make_float4(f0.x, f0.y, f1.x, f1.y);
        *(float4*)(Vs + m * 32 + c * 8 + 4) = make_float4(f2.x, f2.y, f3.x, f3.y);
    }
    __syncthreads();

    int n = tid;
    int gn = bp * NN + n;
    int rot4 = tid & 3;                      // K chunk rotation
    int copyoff = ((tid >> 2) & 1) * 16;     // K copy select
    int rot8 = tid & 7;                      // V chunk rotation
    const float scale = 0.17677669529663687f;
    const __half2 sh2 = __float2half2_rn(scale);

    // Q as fp16 half2, pre-rotated by rot4, scale folded in
    __half2 qh[16];
    const __half* Qg = &g_qkv[t * 3 + 0][gn][h * DK];
    #pragma unroll
    for (int c = 0; c < 4; c++) {
        int cc = (c + rot4) & 3;
        uint4 qv = *(const uint4*)(Qg + cc * 8);
        qh[c * 4 + 0] = __hmul2(u2h2(qv.x), sh2);
        qh[c * 4 + 1] = __hmul2(u2h2(qv.y), sh2);
        qh[c * 4 + 2] = __hmul2(u2h2(qv.z), sh2);
        qh[c * 4 + 3] = __hmul2(u2h2(qv.w), sh2);
    }
    int cnt = g_nnz[t][n];
    float Z = 0.f;
    float4 av[8];
    #pragma unroll
    for (int j = 0; j < 8; j++) av[j] = make_float4(0.f, 0.f, 0.f, 0.f);

    for (int i = 0; i < cnt; i++) {
        int m = g_colsT[t][i][n];        // coalesced: lanes = consecutive n
        float tv = g_valsT[t][i][n];
        const uint32_t* kb = Ks + m * 32 + copyoff;
        __half2 hacc[4];
        #pragma unroll
        for (int c = 0; c < 4; c++) {
            uint4 kk = *(const uint4*)(kb + ((c + rot4) & 3) * 4);
            __half2 a = __hmul2(qh[c * 4 + 0], u2h2(kk.x));
            a = __hfma2(qh[c * 4 + 1], u2h2(kk.y), a);
            a = __hfma2(qh[c * 4 + 2], u2h2(kk.z), a);
            a = __hfma2(qh[c * 4 + 3], u2h2(kk.w), a);
            hacc[c] = a;
        }
        float2 f0 = __half22float2(hacc[0]);
        float2 f1 = __half22float2(hacc[1]);
        float2 f2 = __half22float2(hacc[2]);
        float2 f3 = __half22float2(hacc[3]);
        float s = ((f0.x + f0.y) + (f1.x + f1.y)) + ((f2.x + f2.y) + (f3.x + f3.y));
        float e = __expf(s);
        Z += e;
        float we = tv * e;
        const float* vb = Vs + m * 32;
        #pragma unroll
        for (int j = 0; j < 8; j++) {
            int jj = (j + rot8) & 7;
            float4 v4 = *(const float4*)(vb + jj * 4);
            av[j].x += we * v4.x;
            av[j].y += we * v4.y;
            av[j].z += we * v4.z;
            av[j].w += we * v4.w;
        }
    }
    float inv = 1.f / Z;
    __half* outh = &g_attn[t][gn][h * DK];
    #pragma unroll
    for (int j = 0; j < 8; j += 2) {
        int j0 = (j + rot8) & 7, j1 = (j + 1 + rot8) & 7;
        *(uint2*)(outh + j0 * 4) = make_uint2(pack_h2(av[j].x * inv, av[j].y * inv),
                                              pack_h2(av[j].z * inv, av[j].w * inv));
        *(uint2*)(outh + j1 * 4) = make_uint2(pack_h2(av[j+1].x * inv, av[j+1].y * inv),
                                              pack_h2(av[j+1].z * inv, av[j+1].w * inv));
    }
}

// ===========================================================================
// Kernel 4: output projection via fp16 mma.sync m16n8k16 (K=384 = 3
// accumulated chunks), 512 threads / 16 warps; fused residual + LN.
// ===========================================================================
__global__ void __launch_bounds__(512, 1)
outproj_mma_kernel(const float* __restrict__ X,
                   const float* __restrict__ Wo,
                   const float* __restrict__ gamma,
                   const float* __restrict__ beta,
                   float* __restrict__ out) {
    extern __shared__ uint32_t sm[];
    uint32_t* As = sm;                 // [128][LDH]
    uint32_t* Ws = sm + 128 * LDH;     // [128][LDH]
    float* Ys = (float*)sm;            // reuse (LDP stride) after GEMM
    int tid = threadIdx.x, lane = tid & 31, wid = tid >> 5;
    int mw = wid & 3, nw = wid >> 2;
    int g = lane >> 2, q = lane & 3;
    int row0 = blockIdx.x * 128;

    const uint32_t* abase = As + (mw * 32 + g) * LDH + q;
    const uint32_t* bbase = Ws + (nw * 32 + g) * LDH + q;

    float acc[2][4][4];
    #pragma unroll
    for (int t2 = 0; t2 < 2; t2++)
        #pragma unroll
        for (int j = 0; j < 4; j++)
            #pragma unroll
            for (int e = 0; e < 4; e++) acc[t2][j][e] = 0.f;

    for (int t = 0; t < NT; t++) {
        __syncthreads();
        for (int i = tid; i < 128 * 16; i += 512) {
            int r = i >> 4, c = i & 15;
            uint4 a = *(const uint4*)(&g_attn[t][row0 + r][c * 8]);
            *(uint4*)(As + r * LDH + c * 4) = a;
        }
        for (int i = tid; i < 128 * 32; i += 512) {
            int r = i >> 5, k4 = (i & 31) << 2;
            float4 w = *(const float4*)(Wo + (size_t)r * (NT * DM) + t * DM + k4);
            uint2 p = make_uint2(pack_h2(w.x, w.y), pack_h2(w.z, w.w));
            *(uint2*)(Ws + r * LDH + (k4 >> 1)) = p;
        }
        __syncthreads();
        #pragma unroll
        for (int ks = 0; ks < 8; ks++) {
            int k0 = ks * 8;
            uint32_t a[2][4];
            #pragma unroll
            for (int t2 = 0; t2 < 2; t2++) {
                const uint32_t* ap = abase + t2 * 16 * LDH + k0;
                a[t2][0] = ap[0];            a[t2][1] = ap[8 * LDH];
                a[t2][2] = ap[4];            a[t2][3] = ap[8 * LDH + 4];
            }
            #pragma unroll
            for (int j = 0; j < 4; j++) {
                const uint32_t* bp = bbase + j * 8 * LDH + k0;
                uint32_t b[2]; b[0] = bp[0]; b[1] = bp[4];
                mma16(acc[0][j], a[0], b);
                mma16(acc[1][j], a[1], b);
            }
        }
    }
    __syncthreads();
    #pragma unroll
    for (int t2 = 0; t2 < 2; t2++) {
        int r = mw * 32 + t2 * 16 + g;
        #pragma unroll
        for (int j = 0; j < 4; j++) {
            int c = nw * 32 + j * 8 + q * 2;
            *(float2*)(Ys + r * LDP + c)       = make_float2(acc[t2][j][0], acc[t2][j][1]);
            *(float2*)(Ys + (r + 8) * LDP + c) = make_float2(acc[t2][j][2], acc[t2][j][3]);
        }
    }
    __syncthreads();
    for (int r = wid; r < 128; r += 16) {
        float4 y  = *(float4*)(Ys + r * LDP + lane * 4);
        float4 xv = *(const float4*)(X + (size_t)(row0 + r) * DM + lane * 4);
        float v0 = y.x + xv.x, v1 = y.y + xv.y, v2 = y.z + xv.z, v3 = y.w + xv.w;
        float s  = v0 + v1 + v2 + v3;
        float s2 = v0 * v0 + v1 * v1 + v2 * v2 + v3 * v3;
        #pragma unroll
        for (int off = 16; off; off >>= 1) {
            s  += __shfl_xor_sync(0xffffffffu, s,  off);
            s2 += __shfl_xor_sync(0xffffffffu, s2, off);
        }
        float mu = s * (1.f / DM);
        float var = s2 * (1.f / DM) - mu * mu;
        float rs = rsqrtf(var + 1e-5f);
        float4 gv = *(const float4*)(gamma + lane * 4);
        float4 bv = *(const float4*)(beta + lane * 4);
        float4 res = make_float4((v0 - mu) * rs * gv.x + bv.x,
                                 (v1 - mu) * rs * gv.y + bv.y,
                                 (v2 - mu) * rs * gv.z + bv.z,
                                 (v3 - mu) * rs * gv.w + bv.w);
        *(float4*)(out + (size_t)(row0 + r) * DM + lane * 4) = res;
    }
}

// ===========================================================================
extern "C" void kernel_launch(void* const* d_in, const int* in_sizes, int n_in,
                              void* d_out, int out_size) {
    const float* inputs = (const float*)d_in[0];
    const float* tm     = (const float*)d_in[2];
    const float* Wq     = (const float*)d_in[3];
    const float* Wk     = (const float*)d_in[4];
    const float* Wv     = (const float*)d_in[5];
    const float* Wo     = (const float*)d_in[6];
    const float* gamma  = (const float*)d_in[7];
    const float* beta   = (const float*)d_in[8];
    float* out = (float*)d_out;

    int smem_qkv  = (64 + 128) * LDH * (int)sizeof(uint32_t); // 52224
    int smem_attn = 2 * 512 * 32 * (int)sizeof(uint32_t);     // 131072
    int smem_out  = 2 * 128 * LDH * (int)sizeof(uint32_t);    // 69632
    if (smem_out < 128 * LDP * (int)sizeof(float)) smem_out = 128 * LDP * (int)sizeof(float);
    cudaFuncSetAttribute(qkv_mma_kernel,     cudaFuncAttributeMaxDynamicSharedMemorySize, smem_qkv);
    cudaFuncSetAttribute(attn_kernel,        cudaFuncAttributeMaxDynamicSharedMemorySize, smem_attn);
    cudaFuncSetAttribute(outproj_mma_kernel, cudaFuncAttributeMaxDynamicSharedMemorySize, smem_out);

    convert_kernel<<<(XV + WV + 255) / 256, 256>>>(inputs, Wq, Wk, Wv);
    build_csr_kernel<<<(NT * NN * 32 + 255) / 256, 256>>>(tm);
    qkv_mma_kernel<<<dim3(NROWS / 64, 9), 256, smem_qkv>>>();
    attn_kernel<<<dim3(NH, NT * NB * NP), 512, smem_attn>>>();
    outproj_mma_kernel<<<NROWS / 128, 512, smem_out>>>(inputs, Wo, gamma, beta, out);
}